// round 2
// baseline (speedup 1.0000x reference)
#include <cuda_runtime.h>
#include <cuda_bf16.h>
#include <cstdint>

// Shapes (fixed for this problem)
#define N_NODES 8192
#define D_IN    200
#define D_OUT   128
#define NEG_SLOPE 0.01f

// Scratch (allocation-free rule: __device__ globals)
__device__ float g_dis[N_NODES];           // d^{-1/2}
__device__ float g_B[N_NODES * D_OUT];     // dis[k] * (H W + b)[k, :]

// ---------------------------------------------------------------------------
// Kernel 1: A' = max(sigmoid(A), 0.1), write A' to output, rowsum -> rsqrt
// One block per row, 256 threads, float4 IO. 8192 floats per row.
// ---------------------------------------------------------------------------
__global__ void __launch_bounds__(256) k_sigmoid_rowsum(
    const float* __restrict__ A, float* __restrict__ Aout)
{
    const int row = blockIdx.x;
    const float4* ap = reinterpret_cast<const float4*>(A + (size_t)row * N_NODES);
    float4* op = reinterpret_cast<float4*>(Aout + (size_t)row * N_NODES);

    float sum = 0.0f;
    #pragma unroll 2
    for (int i = threadIdx.x; i < N_NODES / 4; i += 256) {
        float4 v = ap[i];
        float4 s;
        s.x = fmaxf(__fdividef(1.0f, 1.0f + __expf(-v.x)), 0.1f);
        s.y = fmaxf(__fdividef(1.0f, 1.0f + __expf(-v.y)), 0.1f);
        s.z = fmaxf(__fdividef(1.0f, 1.0f + __expf(-v.z)), 0.1f);
        s.w = fmaxf(__fdividef(1.0f, 1.0f + __expf(-v.w)), 0.1f);
        op[i] = s;
        sum += (s.x + s.y) + (s.z + s.w);
    }

    // block reduction (8 warps)
    #pragma unroll
    for (int off = 16; off > 0; off >>= 1)
        sum += __shfl_xor_sync(0xFFFFFFFFu, sum, off);

    __shared__ float ws[8];
    const int wid = threadIdx.x >> 5;
    const int lane = threadIdx.x & 31;
    if (lane == 0) ws[wid] = sum;
    __syncthreads();
    if (threadIdx.x == 0) {
        float tot = 0.0f;
        #pragma unroll
        for (int w = 0; w < 8; w++) tot += ws[w];
        g_dis[row] = rsqrtf(tot);
    }
}

// ---------------------------------------------------------------------------
// Kernel 2: g_B[k,j] = dis[k] * (H[k,:] @ W[:,j] + b[j])
// One block per k, 128 threads (one per j). H row staged in smem; W L2-cached.
// ---------------------------------------------------------------------------
__global__ void __launch_bounds__(128) k_hw(
    const float* __restrict__ H, const float* __restrict__ W,
    const float* __restrict__ b)
{
    const int k = blockIdx.x;
    const int j = threadIdx.x;
    __shared__ float hs[D_IN];
    for (int i = j; i < D_IN; i += 128) hs[i] = H[(size_t)k * D_IN + i];
    __syncthreads();

    float acc = b[j];
    #pragma unroll 8
    for (int i = 0; i < D_IN; i++)
        acc = fmaf(hs[i], W[i * D_OUT + j], acc);

    g_B[(size_t)k * D_OUT + j] = acc * g_dis[k];
}

// ---------------------------------------------------------------------------
// Kernel 3: out[i,j] = leaky( dis[i] * sum_k A'[i,k] * g_B[k,j] )
// tf32 mma.sync m16n8k8. Block tile 64x128, K-tile 16, 8 warps (2x4),
// warp tile 32x32. Register-staged prefetch of next K-tile.
// Grid: 128 blocks (one M-tile each) — one wave on 148 SMs.
// ---------------------------------------------------------------------------
__device__ __forceinline__ uint32_t f2tf32(float x) {
    uint32_t u;
    asm("cvt.rna.tf32.f32 %0, %1;" : "=r"(u) : "f"(x));
    return u;
}

__device__ __forceinline__ void mma_tf32(float* c, const uint32_t* a, const uint32_t* b) {
    asm volatile(
        "mma.sync.aligned.m16n8k8.row.col.f32.tf32.tf32.f32 "
        "{%0,%1,%2,%3}, {%4,%5,%6,%7}, {%8,%9}, {%0,%1,%2,%3};\n"
        : "+f"(c[0]), "+f"(c[1]), "+f"(c[2]), "+f"(c[3])
        : "r"(a[0]), "r"(a[1]), "r"(a[2]), "r"(a[3]), "r"(b[0]), "r"(b[1]));
}

#define BM 64
#define BK 16
#define KTILES (N_NODES / BK)   // 512

__global__ void __launch_bounds__(256) k_gemm(
    const float* __restrict__ Ap, float* __restrict__ out)
{
    __shared__ float As[BM][20];      // pad 20: conflict-free frag loads
    __shared__ float Bs[BK][132];     // pad 132: conflict-free frag loads

    const int t = threadIdx.x;
    const int m0 = blockIdx.x * BM;
    const int wid = t >> 5, lane = t & 31;
    const int wm = wid & 1;           // 0..1 -> 32-row slab
    const int wn = wid >> 1;          // 0..3 -> 32-col slab
    const int lr = lane >> 2;         // 0..7
    const int lc = lane & 3;          // 0..3

    float acc[2][4][4];
    #pragma unroll
    for (int im = 0; im < 2; im++)
        #pragma unroll
        for (int in_ = 0; in_ < 4; in_++)
            #pragma unroll
            for (int r = 0; r < 4; r++) acc[im][in_][r] = 0.0f;

    // gmem load mapping
    const int arow = t >> 2;                 // 0..63
    const int ac4  = (t & 3) * 4;            // 0,4,8,12
    const float* aP = Ap + (size_t)(m0 + arow) * N_NODES + ac4;
    const int br0 = t >> 5, bc0 = (t & 31) * 4;          // idx 0..255
    const int br1 = (t + 256) >> 5, bc1 = bc0;           // idx 256..511
    const float* bP0 = g_B + br0 * D_OUT + bc0;
    const float* bP1 = g_B + br1 * D_OUT + bc1;

    float4 ra  = *reinterpret_cast<const float4*>(aP);
    float4 rb0 = *reinterpret_cast<const float4*>(bP0);
    float4 rb1 = *reinterpret_cast<const float4*>(bP1);

    for (int kt = 0; kt < KTILES; kt++) {
        // stage regs -> smem
        As[arow][ac4 + 0] = ra.x;
        As[arow][ac4 + 1] = ra.y;
        As[arow][ac4 + 2] = ra.z;
        As[arow][ac4 + 3] = ra.w;
        Bs[br0][bc0 + 0] = rb0.x; Bs[br0][bc0 + 1] = rb0.y;
        Bs[br0][bc0 + 2] = rb0.z; Bs[br0][bc0 + 3] = rb0.w;
        Bs[br1][bc1 + 0] = rb1.x; Bs[br1][bc1 + 1] = rb1.y;
        Bs[br1][bc1 + 2] = rb1.z; Bs[br1][bc1 + 3] = rb1.w;
        __syncthreads();

        // prefetch next K-tile (latency overlapped with mma below)
        if (kt + 1 < KTILES) {
            ra  = *reinterpret_cast<const float4*>(aP + (size_t)(kt + 1) * BK);
            rb0 = *reinterpret_cast<const float4*>(bP0 + (size_t)(kt + 1) * BK * D_OUT);
            rb1 = *reinterpret_cast<const float4*>(bP1 + (size_t)(kt + 1) * BK * D_OUT);
        }

        #pragma unroll
        for (int kk = 0; kk < BK; kk += 8) {
            uint32_t af[2][4];
            #pragma unroll
            for (int im = 0; im < 2; im++) {
                const int rb = wm * 32 + im * 16;
                af[im][0] = f2tf32(As[rb + lr    ][kk + lc    ]);
                af[im][1] = f2tf32(As[rb + lr + 8][kk + lc    ]);
                af[im][2] = f2tf32(As[rb + lr    ][kk + lc + 4]);
                af[im][3] = f2tf32(As[rb + lr + 8][kk + lc + 4]);
            }
            uint32_t bf[4][2];
            #pragma unroll
            for (int in_ = 0; in_ < 4; in_++) {
                const int cb = wn * 32 + in_ * 8;
                bf[in_][0] = f2tf32(Bs[kk + lc    ][cb + lr]);
                bf[in_][1] = f2tf32(Bs[kk + lc + 4][cb + lr]);
            }
            #pragma unroll
            for (int im = 0; im < 2; im++)
                #pragma unroll
                for (int in_ = 0; in_ < 4; in_++)
                    mma_tf32(acc[im][in_], af[im], bf[in_]);
        }
        __syncthreads();
    }

    // epilogue: scale by dis[i], LeakyReLU, store
    #pragma unroll
    for (int im = 0; im < 2; im++) {
        const int r0 = m0 + wm * 32 + im * 16 + lr;
        const float d0 = g_dis[r0];
        const float d1 = g_dis[r0 + 8];
        #pragma unroll
        for (int in_ = 0; in_ < 4; in_++) {
            const int c = wn * 32 + in_ * 8 + 2 * lc;
            float v0 = d0 * acc[im][in_][0];
            float v1 = d0 * acc[im][in_][1];
            float v2 = d1 * acc[im][in_][2];
            float v3 = d1 * acc[im][in_][3];
            v0 = (v0 >= 0.0f) ? v0 : NEG_SLOPE * v0;
            v1 = (v1 >= 0.0f) ? v1 : NEG_SLOPE * v1;
            v2 = (v2 >= 0.0f) ? v2 : NEG_SLOPE * v2;
            v3 = (v3 >= 0.0f) ? v3 : NEG_SLOPE * v3;
            out[(size_t)r0 * D_OUT + c]           = v0;
            out[(size_t)r0 * D_OUT + c + 1]       = v1;
            out[(size_t)(r0 + 8) * D_OUT + c]     = v2;
            out[(size_t)(r0 + 8) * D_OUT + c + 1] = v3;
        }
    }
}

// ---------------------------------------------------------------------------
// Launch: output layout = [out (8192*128 floats)] then [A' (8192*8192 floats)]
// (reference returns tuple (out, A) — flattened in order)
// ---------------------------------------------------------------------------
extern "C" void kernel_launch(void* const* d_in, const int* in_sizes, int n_in,
                              void* d_out, int out_size)
{
    const float* H = (const float*)d_in[0];   // [8192, 200]
    const float* A = (const float*)d_in[1];   // [8192, 8192]
    const float* W = (const float*)d_in[2];   // [200, 128]
    const float* b = (const float*)d_in[3];   // [128]

    float* out  = (float*)d_out;                       // [8192, 128]
    float* Aout = out + (size_t)N_NODES * D_OUT;       // [8192, 8192]

    k_sigmoid_rowsum<<<N_NODES, 256>>>(A, Aout);
    k_hw<<<N_NODES, 128>>>(H, W, b);
    k_gemm<<<N_NODES / BM, 256>>>(Aout, out);
}

// round 4
// speedup vs baseline: 2.1603x; 2.1603x over previous
#include <cuda_runtime.h>
#include <cuda_fp16.h>
#include <cstdint>

// Shapes (fixed)
#define N_NODES 8192
#define D_IN    200
#define D_OUT   128
#define NEG_SLOPE 0.01f

// K3 tiling
#define BM      64              // M rows per CTA
#define BKC     64              // K per pipeline chunk (64 fp16 = 128B rows)
#define NCHUNKS (N_NODES / BKC) // 128
#define STAGES  4
#define A_TILE_B  (BM * BKC * 2)        // 8 KB
#define B_TILE_B  (D_OUT * BKC * 2)     // 16 KB
#define STAGE_B   (A_TILE_B + B_TILE_B) // 24 KB
#define SWZ(off) ((off) ^ (((off) >> 3) & 0x70))

// Scratch (__device__ globals: allocation-free rule)
__device__ float  g_dis[N_NODES];                       // d^{-1/2}
__device__ __half g_Ah[(size_t)N_NODES * N_NODES];      // fp16 copy of A'
__device__ __half g_Bt[(size_t)D_OUT * N_NODES];        // [n][k] fp16 dis[k]*(HW+b)

// ---------------------------------------------------------------------------
// Kernel 1: A' = max(sigmoid(A), 0.1) -> fp32 output + fp16 copy; rowsum->rsqrt
// ---------------------------------------------------------------------------
__global__ void __launch_bounds__(256) k_sigmoid_rowsum(
    const float* __restrict__ A, float* __restrict__ Aout)
{
    const int row = blockIdx.x;
    const float4* ap = reinterpret_cast<const float4*>(A + (size_t)row * N_NODES);
    float4* op = reinterpret_cast<float4*>(Aout + (size_t)row * N_NODES);
    uint2* hp = reinterpret_cast<uint2*>(g_Ah + (size_t)row * N_NODES);

    float sum = 0.0f;
    #pragma unroll 2
    for (int i = threadIdx.x; i < N_NODES / 4; i += 256) {
        float4 v = ap[i];
        float4 s;
        s.x = fmaxf(__fdividef(1.0f, 1.0f + __expf(-v.x)), 0.1f);
        s.y = fmaxf(__fdividef(1.0f, 1.0f + __expf(-v.y)), 0.1f);
        s.z = fmaxf(__fdividef(1.0f, 1.0f + __expf(-v.z)), 0.1f);
        s.w = fmaxf(__fdividef(1.0f, 1.0f + __expf(-v.w)), 0.1f);
        op[i] = s;
        __half2 p0 = __floats2half2_rn(s.x, s.y);
        __half2 p1 = __floats2half2_rn(s.z, s.w);
        uint2 u;
        u.x = *reinterpret_cast<uint32_t*>(&p0);
        u.y = *reinterpret_cast<uint32_t*>(&p1);
        hp[i] = u;
        sum += (s.x + s.y) + (s.z + s.w);
    }

    #pragma unroll
    for (int off = 16; off > 0; off >>= 1)
        sum += __shfl_xor_sync(0xFFFFFFFFu, sum, off);

    __shared__ float ws[8];
    const int wid = threadIdx.x >> 5;
    const int lane = threadIdx.x & 31;
    if (lane == 0) ws[wid] = sum;
    __syncthreads();
    if (threadIdx.x == 0) {
        float tot = 0.0f;
        #pragma unroll
        for (int w = 0; w < 8; w++) tot += ws[w];
        g_dis[row] = rsqrtf(tot);
    }
}

// ---------------------------------------------------------------------------
// Kernel 2: g_Bt[n][k] = fp16( dis[k] * (H[k,:]@W[:,n] + b[n]) )  (transposed)
// ---------------------------------------------------------------------------
__global__ void __launch_bounds__(128) k_hw(
    const float* __restrict__ H, const float* __restrict__ W,
    const float* __restrict__ b)
{
    const int k = blockIdx.x;
    const int j = threadIdx.x;
    __shared__ float hs[D_IN];
    for (int i = j; i < D_IN; i += 128) hs[i] = H[(size_t)k * D_IN + i];
    __syncthreads();

    float acc = b[j];
    #pragma unroll 8
    for (int i = 0; i < D_IN; i++)
        acc = fmaf(hs[i], W[i * D_OUT + j], acc);

    g_Bt[(size_t)j * N_NODES + k] = __float2half_rn(acc * g_dis[k]);
}

// ---------------------------------------------------------------------------
// K3: fp16 HMMA GEMM. 128 CTAs (M=64 each), N=128 full, K=8192.
// cp.async 4-stage pipeline, ldmatrix, mma.m16n8k16.f16.f32.
// Warp grid 2(m)x4(n): warp tile 32x32.
// ---------------------------------------------------------------------------
__device__ __forceinline__ uint32_t s2u(const void* p) {
    uint32_t a;
    asm("{ .reg .u64 t; cvta.to.shared.u64 t, %1; cvt.u32.u64 %0, t; }"
        : "=r"(a) : "l"(p));
    return a;
}
__device__ __forceinline__ void cp16(uint32_t dst, const void* src) {
    asm volatile("cp.async.cg.shared.global [%0], [%1], 16;"
                 :: "r"(dst), "l"(src) : "memory");
}
__device__ __forceinline__ void ldsm4(uint32_t* r, uint32_t addr) {
    asm volatile("ldmatrix.sync.aligned.m8n8.x4.shared.b16 {%0,%1,%2,%3}, [%4];"
                 : "=r"(r[0]), "=r"(r[1]), "=r"(r[2]), "=r"(r[3]) : "r"(addr));
}
__device__ __forceinline__ void hmma(float* d, const uint32_t* a,
                                     uint32_t b0, uint32_t b1) {
    asm volatile(
        "mma.sync.aligned.m16n8k16.row.col.f32.f16.f16.f32 "
        "{%0,%1,%2,%3},{%4,%5,%6,%7},{%8,%9},{%0,%1,%2,%3};"
        : "+f"(d[0]), "+f"(d[1]), "+f"(d[2]), "+f"(d[3])
        : "r"(a[0]), "r"(a[1]), "r"(a[2]), "r"(a[3]), "r"(b0), "r"(b1));
}

__global__ void __launch_bounds__(256, 1) k_gemm_h(float* __restrict__ out)
{
    extern __shared__ __align__(1024) char dsm[];   // STAGES * 24KB = 96KB
    const int t   = threadIdx.x;
    const int wid = t >> 5, lane = t & 31;
    const int wm  = wid & 1;          // m slab (0..1) * 32
    const int wn  = wid >> 1;         // n slab (0..3) * 32
    const int m0  = blockIdx.x * BM;
    const uint32_t smBase = s2u(dsm);

    // ---- staging maps (per thread): 16B chunks, rows of 128B with XOR swizzle
    const int sr  = t >> 3;           // 0..31
    const int sc  = (t & 7) * 16;     // byte col in 128B row
    const __half* srcA = g_Ah + (size_t)(m0 + sr) * N_NODES + (t & 7) * 8;
    const __half* srcB = g_Bt + (size_t)sr * N_NODES + (t & 7) * 8;
    const uint32_t dstA = SWZ(sr * 128 + sc);           // + 4096 for rows+32
    const uint32_t dstB = SWZ(sr * 128 + sc);           // + 4096 per 32 rows

    // ---- ldmatrix address components (row fixed per fragment)
    const int lr16 = lane & 15;
    const int lhalf = (lane >> 4) * 16;   // 16B col select
    uint32_t aBase[2], bBase[2];
    #pragma unroll
    for (int mt = 0; mt < 2; mt++) {
        int r = wm * 32 + mt * 16 + lr16;
        aBase[mt] = r * 128 + lhalf;      // SWZ applied after adding kk*32
    }
    #pragma unroll
    for (int bt = 0; bt < 2; bt++) {
        int r = wn * 32 + bt * 16 + lr16;
        bBase[bt] = r * 128 + lhalf;
    }

    float acc[2][4][4];
    #pragma unroll
    for (int mt = 0; mt < 2; mt++)
        #pragma unroll
        for (int nt = 0; nt < 4; nt++)
            #pragma unroll
            for (int r = 0; r < 4; r++) acc[mt][nt][r] = 0.0f;

    // ---- prologue: issue STAGES-1 chunks
    #pragma unroll
    for (int c = 0; c < STAGES - 1; c++) {
        const uint32_t sA = smBase + c * STAGE_B;
        const uint32_t sB = sA + A_TILE_B;
        const int ko = c * BKC;
        cp16(sA + dstA,        srcA + ko);
        cp16(sA + dstA + 4096, srcA + ko + 32ull * N_NODES);
        #pragma unroll
        for (int rb = 0; rb < 4; rb++)
            cp16(sB + dstB + rb * 4096, srcB + ko + (size_t)rb * 32 * N_NODES);
        asm volatile("cp.async.commit_group;" ::: "memory");
    }

    for (int c = 0; c < NCHUNKS; c++) {
        asm volatile("cp.async.wait_group %0;" :: "n"(STAGES - 2) : "memory");
        __syncthreads();

        const uint32_t sA = smBase + (c & (STAGES - 1)) * STAGE_B;
        const uint32_t sB = sA + A_TILE_B;

        #pragma unroll
        for (int kk = 0; kk < BKC / 16; kk++) {
            uint32_t aF[2][4], bF[2][4];
            #pragma unroll
            for (int mt = 0; mt < 2; mt++)
                ldsm4(aF[mt], sA + SWZ(aBase[mt] + kk * 32));
            #pragma unroll
            for (int bt = 0; bt < 2; bt++)
                ldsm4(bF[bt], sB + SWZ(bBase[bt] + kk * 32));
            #pragma unroll
            for (int mt = 0; mt < 2; mt++)
                #pragma unroll
                for (int nt = 0; nt < 4; nt++)
                    hmma(acc[mt][nt], aF[mt],
                         bF[nt >> 1][nt & 1], bF[nt >> 1][(nt & 1) + 2]);
        }

        // issue chunk c + STAGES-1
        const int cn = c + STAGES - 1;
        if (cn < NCHUNKS) {
            const uint32_t nA = smBase + (cn & (STAGES - 1)) * STAGE_B;
            const uint32_t nB = nA + A_TILE_B;
            const int ko = cn * BKC;
            cp16(nA + dstA,        srcA + ko);
            cp16(nA + dstA + 4096, srcA + ko + 32ull * N_NODES);
            #pragma unroll
            for (int rb = 0; rb < 4; rb++)
                cp16(nB + dstB + rb * 4096, srcB + ko + (size_t)rb * 32 * N_NODES);
        }
        asm volatile("cp.async.commit_group;" ::: "memory");
    }

    // ---- epilogue: scale by dis[i], LeakyReLU, store float2 pairs
    const int gid = lane >> 2;          // 0..7
    const int cid = (lane & 3) * 2;     // 0,2,4,6
    #pragma unroll
    for (int mt = 0; mt < 2; mt++) {
        const int r0 = m0 + wm * 32 + mt * 16 + gid;
        const float d0 = g_dis[r0];
        const float d1 = g_dis[r0 + 8];
        #pragma unroll
        for (int nt = 0; nt < 4; nt++) {
            const int col = wn * 32 + nt * 8 + cid;
            float v0 = d0 * acc[mt][nt][0];
            float v1 = d0 * acc[mt][nt][1];
            float v2 = d1 * acc[mt][nt][2];
            float v3 = d1 * acc[mt][nt][3];
            v0 = (v0 >= 0.0f) ? v0 : NEG_SLOPE * v0;
            v1 = (v1 >= 0.0f) ? v1 : NEG_SLOPE * v1;
            v2 = (v2 >= 0.0f) ? v2 : NEG_SLOPE * v2;
            v3 = (v3 >= 0.0f) ? v3 : NEG_SLOPE * v3;
            *reinterpret_cast<float2*>(out + (size_t)r0 * D_OUT + col)
                = make_float2(v0, v1);
            *reinterpret_cast<float2*>(out + (size_t)(r0 + 8) * D_OUT + col)
                = make_float2(v2, v3);
        }
    }
}

// ---------------------------------------------------------------------------
extern "C" void kernel_launch(void* const* d_in, const int* in_sizes, int n_in,
                              void* d_out, int out_size)
{
    const float* H = (const float*)d_in[0];   // [8192, 200]
    const float* A = (const float*)d_in[1];   // [8192, 8192]
    const float* W = (const float*)d_in[2];   // [200, 128]
    const float* b = (const float*)d_in[3];   // [128]

    float* out  = (float*)d_out;                     // [8192, 128]
    float* Aout = out + (size_t)N_NODES * D_OUT;     // [8192, 8192] exact A'

    k_sigmoid_rowsum<<<N_NODES, 256>>>(A, Aout);
    k_hw<<<N_NODES, 128>>>(H, W, b);

    cudaFuncSetAttribute(k_gemm_h, cudaFuncAttributeMaxDynamicSharedMemorySize,
                         STAGES * STAGE_B);
    k_gemm_h<<<N_NODES / BM, 256, STAGES * STAGE_B>>>(out);
}